// round 6
// baseline (speedup 1.0000x reference)
#include <cuda_runtime.h>
#include <math.h>
#include <stdint.h>

// Problem constants
#define BB 32
#define TT 512
#define DD 512
#define UU 1024
#define NC 4096   // 4*U packed gate columns, layout [unit][gate], gate order f,i,g,o

#define NCTA 128      // persistent CTAs (1 per SM)
#define CU 32         // gate-cols per CTA (8 units)
#define NSLICE 8      // K-split factor
#define KSL 128       // k per slice (1024/8)

// -------- device scratch --------
__device__ float g_Whp[1024 * 4096];          // [k][u*4+g] recurrent weights (packed)
__device__ float g_Wxp[512 * 4096];           // [d][u*4+g] input weights (packed)
__device__ float g_bp[4096];                  // packed biases
__device__ float g_zx[(size_t)TT * BB * NC];  // [t][b][u*4+g]  x-part (+bias)
__device__ float g_hT[2][UU * BB];            // ping-pong hidden state, layout [u][b]
__device__ unsigned g_flags[NCTA * 32];       // per-CTA step flags (padded: 128B apart)

// -------- f32x2 helpers --------
__device__ __forceinline__ void fma2(unsigned long long& acc, unsigned long long a,
                                     unsigned long long b) {
    asm("fma.rn.f32x2 %0, %1, %2, %3;" : "=l"(acc) : "l"(a), "l"(b), "l"(acc));
}
__device__ __forceinline__ void add2(unsigned long long& acc, unsigned long long a) {
    asm("add.rn.f32x2 %0, %1, %2;" : "=l"(acc) : "l"(acc), "l"(a));
}
__device__ __forceinline__ unsigned long long dup2(float x) {
    unsigned long long r;
    asm("mov.b64 %0, {%1, %1};" : "=l"(r) : "f"(x));
    return r;
}
__device__ __forceinline__ float2 unpack2(unsigned long long v) {
    float2 r;
    asm("mov.b64 {%0, %1}, %2;" : "=f"(r.x), "=f"(r.y) : "l"(v));
    return r;
}
__device__ __forceinline__ float sigmoidf_(float x) {
    return 1.0f / (1.0f + __expf(-x));
}
__device__ __forceinline__ float tanhf_(float x) {
    return 1.0f - 2.0f / (__expf(2.0f * x) + 1.0f);
}

// -------- barrier primitives --------
__device__ __forceinline__ void st_release(unsigned* p, unsigned v) {
    asm volatile("st.release.gpu.u32 [%0], %1;" :: "l"(p), "r"(v) : "memory");
}
__device__ __forceinline__ unsigned ld_acquire(unsigned* p) {
    unsigned v;
    asm volatile("ld.acquire.gpu.u32 %0, [%1];" : "=r"(v) : "l"(p) : "memory");
    return v;
}

// ===========================================================================
// Prep: pack weights gate-interleaved, pack biases, zero h0 + flags
// ===========================================================================
__global__ void prep_kernel(const float* __restrict__ Wf, const float* __restrict__ Wi,
                            const float* __restrict__ Wc, const float* __restrict__ Wo,
                            const float* __restrict__ bf, const float* __restrict__ bi,
                            const float* __restrict__ bc, const float* __restrict__ bo) {
    int idx = blockIdx.x * blockDim.x + threadIdx.x;
    int stride = gridDim.x * blockDim.x;
    for (int i = idx; i < NCTA * 32; i += stride) g_flags[i] = 0u;
    for (int i = idx; i < 1024 * 1024; i += stride) {
        int k = i >> 10, u = i & 1023;
        int s = k * 1024 + u;
        float4 v = make_float4(Wf[s], Wi[s], Wc[s], Wo[s]);
        *(float4*)&g_Whp[((size_t)k << 12) + (u << 2)] = v;
    }
    for (int i = idx; i < 512 * 1024; i += stride) {
        int d = i >> 10, u = i & 1023;
        int s = (1024 + d) * 1024 + u;
        float4 v = make_float4(Wf[s], Wi[s], Wc[s], Wo[s]);
        *(float4*)&g_Wxp[((size_t)d << 12) + (u << 2)] = v;
    }
    for (int u = idx; u < 1024; u += stride)
        *(float4*)&g_bp[u << 2] = make_float4(bf[u], bi[u], bc[u], bo[u]);
    for (int i = idx; i < UU * BB; i += stride) g_hT[0][i] = 0.0f;
}

// ===========================================================================
// zx GEMM (unchanged):  zx[t][b][c] = bias[c] + sum_d x[b][t][d] * Wxp[d][c]
// ===========================================================================
#define ZBM 64
#define ZBN 64
#define ZBK 32
#define ZAPAD 68

__global__ __launch_bounds__(256) void zx_kernel(const float* __restrict__ x) {
    __shared__ __align__(16) float As[ZBK][ZAPAD];
    __shared__ __align__(16) float Bs[ZBK][ZBN];

    int row0 = blockIdx.x * ZBM;
    int c0 = blockIdx.y * ZBN;
    int tid = threadIdx.x;
    int tx = tid & 15;
    int ty = tid >> 4;

    unsigned long long acc01[4], acc23[4];
#pragma unroll
    for (int r = 0; r < 4; r++) { acc01[r] = 0ull; acc23[r] = 0ull; }

    int ar = tid >> 2, akq = tid & 3;
    int bkr = tid >> 3, bcq = tid & 7;

    for (int k0 = 0; k0 < DD; k0 += ZBK) {
        __syncthreads();
#pragma unroll
        for (int i = 0; i < 2; i++) {
            int koff = (akq + i * 4) * 4;
            int row = row0 + ar;
            int t = row >> 5, b = row & 31;
            float4 v = *(const float4*)&x[((size_t)b * TT + t) * DD + k0 + koff];
            As[koff + 0][ar] = v.x;
            As[koff + 1][ar] = v.y;
            As[koff + 2][ar] = v.z;
            As[koff + 3][ar] = v.w;
        }
#pragma unroll
        for (int i = 0; i < 2; i++) {
            int coff = (bcq + i * 8) * 4;
            float4 v = *(const float4*)&g_Wxp[(size_t)(k0 + bkr) * NC + c0 + coff];
            *(float4*)&Bs[bkr][coff] = v;
        }
        __syncthreads();

#pragma unroll
        for (int kk = 0; kk < ZBK; kk++) {
            float4 a = *(const float4*)&As[kk][ty * 4];
            ulonglong2 bv = *(const ulonglong2*)&Bs[kk][tx * 4];
            unsigned long long a0 = dup2(a.x);
            unsigned long long a1 = dup2(a.y);
            unsigned long long a2 = dup2(a.z);
            unsigned long long a3 = dup2(a.w);
            fma2(acc01[0], a0, bv.x); fma2(acc23[0], a0, bv.y);
            fma2(acc01[1], a1, bv.x); fma2(acc23[1], a1, bv.y);
            fma2(acc01[2], a2, bv.x); fma2(acc23[2], a2, bv.y);
            fma2(acc01[3], a3, bv.x); fma2(acc23[3], a3, bv.y);
        }
    }

    float4 bias = *(const float4*)&g_bp[c0 + tx * 4];
#pragma unroll
    for (int r = 0; r < 4; r++) {
        float2 v01 = unpack2(acc01[r]);
        float2 v23 = unpack2(acc23[r]);
        float4 o;
        o.x = v01.x + bias.x;
        o.y = v01.y + bias.y;
        o.z = v23.x + bias.z;
        o.w = v23.y + bias.w;
        int row = row0 + ty * 4 + r;
        *(float4*)&g_zx[(size_t)row * NC + c0 + tx * 4] = o;
    }
}

// ===========================================================================
// Persistent recurrent kernel. 256 threads, NSLICE=8 x KSL=128.
// Thread GEMM role: slice s = tid>>5; lane: cg = (lane>>4) col group (16 cols),
// bp = lane&15 batch pair (batches 2bp, 2bp+1). 16 FFMA2 per k per thread.
// Tail: 8 STS.128 partials, 16 LDS.64 + add2 reduce, flag barrier.
// smem: ws[1024][32] (128KB) + red[8][16][32] ull (32KB) = 160KB
// ===========================================================================
__global__ __launch_bounds__(256, 1) void lstm_persistent(float* __restrict__ out) {
    extern __shared__ __align__(16) float smem[];
    float* ws = smem;                                                   // 128KB
    unsigned long long* red = (unsigned long long*)(smem + 1024 * 32);  // 32KB

    const int tid = threadIdx.x;
    const int cu = blockIdx.x;

    // --- load this CTA's weight slice into smem (once) ---
    {
        const float4* src = (const float4*)(g_Whp + (size_t)cu * CU);
        float4* dst = (float4*)ws;
        for (int i = tid; i < 1024 * 8; i += 256) {
            int k = i >> 3, q = i & 7;
            dst[k * 8 + q] = src[(size_t)k * 1024 + q];
        }
    }

    // --- GEMM roles ---
    const int s = tid >> 5;          // k-slice 0..7
    const int lane = tid & 31;
    const int cg = lane >> 4;        // col group (16 cols)
    const int bp = lane & 15;        // batch pair: batches 2bp, 2bp+1
    const int c0 = cg * 16;
    const int kb = s * KSL;

    // --- gate-math roles ---
    const int up = tid >> 5;         // unit-in-CTA 0..7
    const int gb = tid & 31;         // batch 0..31
    const int ug = cu * 8 + up;      // global unit

    float c_state = 0.0f;

    __syncthreads();                 // weights ready

    for (int t = 0; t < TT; t++) {
        const float* __restrict__ hT = g_hT[t & 1];
        float* __restrict__ hTo = g_hT[(t + 1) & 1];

        // Prefetch zx for this step (hidden behind the GEMM)
        float4 zx4 = __ldcg((const float4*)&g_zx[((size_t)t * BB + gb) * NC + ug * 4]);

        // ---- GEMM: acc[bi][p] over k in [kb, kb+128) ----
        unsigned long long acc[2][8];
#pragma unroll
        for (int bi = 0; bi < 2; bi++)
#pragma unroll
            for (int p = 0; p < 8; p++) acc[bi][p] = 0ull;

        const float2* hp = (const float2*)(hT + (size_t)kb * 32) + bp;  // stride 16 float2/k
        const ulonglong2* wrow0 = (const ulonglong2*)(ws + kb * 32 + c0);

        float2 bufA[8], bufB[8];
#pragma unroll
        for (int j = 0; j < 8; j++) bufA[j] = __ldcg(hp + (size_t)j * 16);

#pragma unroll
        for (int kc = 0; kc < KSL; kc += 16) {
#pragma unroll
            for (int j = 0; j < 8; j++) bufB[j] = __ldcg(hp + (size_t)(kc + 8 + j) * 16);
#pragma unroll
            for (int j = 0; j < 8; j++) {
                float2 hv = bufA[j];
                unsigned long long h0 = dup2(hv.x), h1 = dup2(hv.y);
                const ulonglong2* wr = wrow0 + (size_t)(kc + j) * 8;
#pragma unroll
                for (int q = 0; q < 4; q++) {
                    ulonglong2 w2 = wr[q];
                    fma2(acc[0][2 * q], h0, w2.x); fma2(acc[0][2 * q + 1], h0, w2.y);
                    fma2(acc[1][2 * q], h1, w2.x); fma2(acc[1][2 * q + 1], h1, w2.y);
                }
            }
            if (kc + 16 < KSL) {
#pragma unroll
                for (int j = 0; j < 8; j++) bufA[j] = __ldcg(hp + (size_t)(kc + 16 + j) * 16);
            }
#pragma unroll
            for (int j = 0; j < 8; j++) {
                float2 hv = bufB[j];
                unsigned long long h0 = dup2(hv.x), h1 = dup2(hv.y);
                const ulonglong2* wr = wrow0 + (size_t)(kc + 8 + j) * 8;
#pragma unroll
                for (int q = 0; q < 4; q++) {
                    ulonglong2 w2 = wr[q];
                    fma2(acc[0][2 * q], h0, w2.x); fma2(acc[0][2 * q + 1], h0, w2.y);
                    fma2(acc[1][2 * q], h1, w2.x); fma2(acc[1][2 * q + 1], h1, w2.y);
                }
            }
        }

        // ---- write partials: red[s][colpair][batch], STS.128 pairs ----
#pragma unroll
        for (int p = 0; p < 8; p++) {
            ulonglong2 v;
            v.x = acc[0][p];
            v.y = acc[1][p];
            *(ulonglong2*)&red[((size_t)s * 16 + cg * 8 + p) * 32 + 2 * bp] = v;
        }
        __syncthreads();

        // ---- reduce + gate math: thread = (unit up, batch gb) ----
        float h_new;
        {
            unsigned long long fiv = 0ull, gov = 0ull;
#pragma unroll
            for (int ss = 0; ss < NSLICE; ss++) {
                add2(fiv, red[((size_t)ss * 16 + 2 * up) * 32 + gb]);
                add2(gov, red[((size_t)ss * 16 + 2 * up + 1) * 32 + gb]);
            }
            float2 fi = unpack2(fiv);
            float2 go = unpack2(gov);
            float zf = fi.x + zx4.x;
            float zi = fi.y + zx4.y;
            float zg = go.x + zx4.z;
            float zo = go.y + zx4.w;

            float f = sigmoidf_(zf);
            float ii = sigmoidf_(zi);
            float g = tanhf_(zg);
            float o = sigmoidf_(zo);
            c_state = f * c_state + ii * g;
            h_new = o * tanhf_(c_state);

            __stcg(&hTo[ug * 32 + gb], h_new);
        }

        // ---- distributed flag barrier ----
        __syncthreads();   // all h stores issued, red consumed
        if (tid == 0) st_release(&g_flags[cu * 32], (unsigned)(t + 1));

        // Overlap with barrier: out[] store (no cross-CTA consumer)
        out[((size_t)gb * TT + t) * UU + ug] = h_new;

        if (tid < NCTA) {
            unsigned target = (unsigned)(t + 1);
            while (ld_acquire(&g_flags[tid * 32]) < target) {}
        }
        __syncthreads();
    }
}

// ===========================================================================
// Launch
// ===========================================================================
extern "C" void kernel_launch(void* const* d_in, const int* in_sizes, int n_in,
                              void* d_out, int out_size) {
    const float* data = (const float*)d_in[0];
    const float* Wf = (const float*)d_in[1];
    const float* bf = (const float*)d_in[2];
    const float* Wi = (const float*)d_in[3];
    const float* bi = (const float*)d_in[4];
    const float* Wc = (const float*)d_in[5];
    const float* bc = (const float*)d_in[6];
    const float* Wo = (const float*)d_in[7];
    const float* bo = (const float*)d_in[8];
    float* out = (float*)d_out;

    prep_kernel<<<512, 256>>>(Wf, Wi, Wc, Wo, bf, bi, bc, bo);

    dim3 zgrid(TT * BB / ZBM, NC / ZBN);
    zx_kernel<<<zgrid, 256>>>(data);

    static int smem_set = 0;
    const int smem_bytes = 1024 * 32 * 4 + NSLICE * 16 * 32 * 8;  // 128KB + 32KB = 160KB
    if (!smem_set) {
        cudaFuncSetAttribute(lstm_persistent,
                             cudaFuncAttributeMaxDynamicSharedMemorySize, smem_bytes);
        smem_set = 1;
    }
    lstm_persistent<<<NCTA, 256, smem_bytes>>>(out);
}

// round 7
// speedup vs baseline: 1.0412x; 1.0412x over previous
#include <cuda_runtime.h>
#include <math.h>
#include <stdint.h>

// Problem constants
#define BB 32
#define TT 512
#define DD 512
#define UU 1024
#define NC 4096   // 4*U packed gate columns, layout [unit][gate], gate order f,i,g,o

#define NCTA 128      // persistent CTAs (1 per SM)
#define CU 32         // gate-cols per CTA (8 units)
#define NSLICE 16     // K-split factor
#define KSL 64        // k per slice (1024/16)

// -------- device scratch --------
__device__ float g_Whp[1024 * 4096];          // [k][u*4+g] recurrent weights (packed)
__device__ float g_Wxp[512 * 4096];           // [d][u*4+g] input weights (packed)
__device__ float g_bp[4096];                  // packed biases
__device__ float g_zx[(size_t)TT * BB * NC];  // [t][b][u*4+g]  x-part (+bias)
__device__ float g_hT[2][UU * BB];            // ping-pong hidden state, layout [u][b]
__device__ unsigned g_flags[NCTA * 32];       // per-CTA step flags (128B apart)

// -------- f32x2 helpers --------
__device__ __forceinline__ void fma2(unsigned long long& acc, unsigned long long a,
                                     unsigned long long b) {
    asm("fma.rn.f32x2 %0, %1, %2, %3;" : "=l"(acc) : "l"(a), "l"(b), "l"(acc));
}
__device__ __forceinline__ void add2(unsigned long long& acc, unsigned long long a) {
    asm("add.rn.f32x2 %0, %1, %2;" : "=l"(acc) : "l"(acc), "l"(a));
}
__device__ __forceinline__ unsigned long long dup2(float x) {
    unsigned long long r;
    asm("mov.b64 %0, {%1, %1};" : "=l"(r) : "f"(x));
    return r;
}
__device__ __forceinline__ float2 unpack2(unsigned long long v) {
    float2 r;
    asm("mov.b64 {%0, %1}, %2;" : "=f"(r.x), "=f"(r.y) : "l"(v));
    return r;
}
__device__ __forceinline__ float sigmoidf_(float x) {
    return 1.0f / (1.0f + __expf(-x));
}
__device__ __forceinline__ float tanhf_(float x) {
    return 1.0f - 2.0f / (__expf(2.0f * x) + 1.0f);
}

// -------- barrier primitives --------
__device__ __forceinline__ void st_release(unsigned* p, unsigned v) {
    asm volatile("st.release.gpu.u32 [%0], %1;" :: "l"(p), "r"(v) : "memory");
}
__device__ __forceinline__ unsigned ld_acquire(unsigned* p) {
    unsigned v;
    asm volatile("ld.acquire.gpu.u32 %0, [%1];" : "=r"(v) : "l"(p) : "memory");
    return v;
}

// ===========================================================================
// Prep: pack weights gate-interleaved, pack biases, zero h0 + flags
// ===========================================================================
__global__ void prep_kernel(const float* __restrict__ Wf, const float* __restrict__ Wi,
                            const float* __restrict__ Wc, const float* __restrict__ Wo,
                            const float* __restrict__ bf, const float* __restrict__ bi,
                            const float* __restrict__ bc, const float* __restrict__ bo) {
    int idx = blockIdx.x * blockDim.x + threadIdx.x;
    int stride = gridDim.x * blockDim.x;
    for (int i = idx; i < NCTA * 32; i += stride) g_flags[i] = 0u;
    for (int i = idx; i < 1024 * 1024; i += stride) {
        int k = i >> 10, u = i & 1023;
        int s = k * 1024 + u;
        float4 v = make_float4(Wf[s], Wi[s], Wc[s], Wo[s]);
        *(float4*)&g_Whp[((size_t)k << 12) + (u << 2)] = v;
    }
    for (int i = idx; i < 512 * 1024; i += stride) {
        int d = i >> 10, u = i & 1023;
        int s = (1024 + d) * 1024 + u;
        float4 v = make_float4(Wf[s], Wi[s], Wc[s], Wo[s]);
        *(float4*)&g_Wxp[((size_t)d << 12) + (u << 2)] = v;
    }
    for (int u = idx; u < 1024; u += stride)
        *(float4*)&g_bp[u << 2] = make_float4(bf[u], bi[u], bc[u], bo[u]);
    for (int i = idx; i < UU * BB; i += stride) g_hT[0][i] = 0.0f;
}

// ===========================================================================
// zx GEMM (unchanged):  zx[t][b][c] = bias[c] + sum_d x[b][t][d] * Wxp[d][c]
// ===========================================================================
#define ZBM 64
#define ZBN 64
#define ZBK 32
#define ZAPAD 68

__global__ __launch_bounds__(256) void zx_kernel(const float* __restrict__ x) {
    __shared__ __align__(16) float As[ZBK][ZAPAD];
    __shared__ __align__(16) float Bs[ZBK][ZBN];

    int row0 = blockIdx.x * ZBM;
    int c0 = blockIdx.y * ZBN;
    int tid = threadIdx.x;
    int tx = tid & 15;
    int ty = tid >> 4;

    unsigned long long acc01[4], acc23[4];
#pragma unroll
    for (int r = 0; r < 4; r++) { acc01[r] = 0ull; acc23[r] = 0ull; }

    int ar = tid >> 2, akq = tid & 3;
    int bkr = tid >> 3, bcq = tid & 7;

    for (int k0 = 0; k0 < DD; k0 += ZBK) {
        __syncthreads();
#pragma unroll
        for (int i = 0; i < 2; i++) {
            int koff = (akq + i * 4) * 4;
            int row = row0 + ar;
            int t = row >> 5, b = row & 31;
            float4 v = *(const float4*)&x[((size_t)b * TT + t) * DD + k0 + koff];
            As[koff + 0][ar] = v.x;
            As[koff + 1][ar] = v.y;
            As[koff + 2][ar] = v.z;
            As[koff + 3][ar] = v.w;
        }
#pragma unroll
        for (int i = 0; i < 2; i++) {
            int coff = (bcq + i * 8) * 4;
            float4 v = *(const float4*)&g_Wxp[(size_t)(k0 + bkr) * NC + c0 + coff];
            *(float4*)&Bs[bkr][coff] = v;
        }
        __syncthreads();

#pragma unroll
        for (int kk = 0; kk < ZBK; kk++) {
            float4 a = *(const float4*)&As[kk][ty * 4];
            ulonglong2 bv = *(const ulonglong2*)&Bs[kk][tx * 4];
            unsigned long long a0 = dup2(a.x);
            unsigned long long a1 = dup2(a.y);
            unsigned long long a2 = dup2(a.z);
            unsigned long long a3 = dup2(a.w);
            fma2(acc01[0], a0, bv.x); fma2(acc23[0], a0, bv.y);
            fma2(acc01[1], a1, bv.x); fma2(acc23[1], a1, bv.y);
            fma2(acc01[2], a2, bv.x); fma2(acc23[2], a2, bv.y);
            fma2(acc01[3], a3, bv.x); fma2(acc23[3], a3, bv.y);
        }
    }

    float4 bias = *(const float4*)&g_bp[c0 + tx * 4];
#pragma unroll
    for (int r = 0; r < 4; r++) {
        float2 v01 = unpack2(acc01[r]);
        float2 v23 = unpack2(acc23[r]);
        float4 o;
        o.x = v01.x + bias.x;
        o.y = v01.y + bias.y;
        o.z = v23.x + bias.z;
        o.w = v23.y + bias.w;
        int row = row0 + ty * 4 + r;
        *(float4*)&g_zx[(size_t)row * NC + c0 + tx * 4] = o;
    }
}

// ===========================================================================
// Persistent recurrent kernel: exact R5 GEMM core (NSLICE=16, 4b x 16c tile,
// float4 h loads, depth-8 prefetch). Tail-only changes vs R5:
//   - distributed flag barrier (st.release + parallel per-flag polls)
//   - STS.128 packed partial stores (16 instead of 32 per thread)
// smem: ws[1024][32] (128KB) + red[16][16][32] ull (64KB) = 192KB
// ===========================================================================
__global__ __launch_bounds__(256, 1) void lstm_persistent(float* __restrict__ out) {
    extern __shared__ __align__(16) float smem[];
    float* ws = smem;                                                   // 128KB
    unsigned long long* red = (unsigned long long*)(smem + 1024 * 32);  // 64KB

    const int tid = threadIdx.x;
    const int cu = blockIdx.x;

    // --- load this CTA's weight slice into smem (once) ---
    {
        const float4* src = (const float4*)(g_Whp + (size_t)cu * CU);
        float4* dst = (float4*)ws;
        for (int i = tid; i < 1024 * 8; i += 256) {
            int k = i >> 3, q = i & 7;
            dst[k * 8 + q] = src[(size_t)k * 1024 + q];
        }
    }

    // --- GEMM roles (R5) ---
    const int s = tid >> 4;          // k-slice 0..15
    const int cov = tid & 15;
    const int bg = cov & 7;          // batch group (4 batches)
    const int cg = cov >> 3;         // col group (16 cols)
    const int b0 = bg * 4;
    const int c0 = cg * 16;
    const int kb = s * KSL;

    // --- gate-math roles ---
    const int up = tid >> 5;         // unit-in-CTA 0..7
    const int gb = tid & 31;         // batch 0..31
    const int ug = cu * 8 + up;      // global unit

    float c_state = 0.0f;

    __syncthreads();                 // weights ready

    for (int t = 0; t < TT; t++) {
        const float* __restrict__ hT = g_hT[t & 1];
        float* __restrict__ hTo = g_hT[(t + 1) & 1];

        // Prefetch zx for this step (hidden behind the GEMM)
        float4 zx4 = __ldcg((const float4*)&g_zx[((size_t)t * BB + gb) * NC + ug * 4]);

        // ---- GEMM: acc[b][cp] over k in [kb, kb+64) ----
        unsigned long long acc[4][8];
#pragma unroll
        for (int b = 0; b < 4; b++)
#pragma unroll
            for (int p = 0; p < 8; p++) acc[b][p] = 0ull;

        const float4* hp = (const float4*)(hT + (size_t)kb * 32 + b0);
        const ulonglong2* wrow0 = (const ulonglong2*)(ws + kb * 32 + c0);

        // Deep double-buffer: 8 k-iters per buffer
        float4 bufA[8], bufB[8];
#pragma unroll
        for (int j = 0; j < 8; j++) bufA[j] = __ldcg(hp + (size_t)j * 8);

#pragma unroll
        for (int kc = 0; kc < KSL; kc += 16) {
#pragma unroll
            for (int j = 0; j < 8; j++) bufB[j] = __ldcg(hp + (size_t)(kc + 8 + j) * 8);
#pragma unroll
            for (int j = 0; j < 8; j++) {
                float4 hv = bufA[j];
                unsigned long long h0 = dup2(hv.x), h1 = dup2(hv.y);
                unsigned long long h2 = dup2(hv.z), h3 = dup2(hv.w);
                const ulonglong2* wr = wrow0 + (size_t)(kc + j) * 8;
#pragma unroll
                for (int q = 0; q < 4; q++) {
                    ulonglong2 w2 = wr[q];
                    fma2(acc[0][2 * q], h0, w2.x); fma2(acc[0][2 * q + 1], h0, w2.y);
                    fma2(acc[1][2 * q], h1, w2.x); fma2(acc[1][2 * q + 1], h1, w2.y);
                    fma2(acc[2][2 * q], h2, w2.x); fma2(acc[2][2 * q + 1], h2, w2.y);
                    fma2(acc[3][2 * q], h3, w2.x); fma2(acc[3][2 * q + 1], h3, w2.y);
                }
            }
            if (kc + 16 < KSL) {
#pragma unroll
                for (int j = 0; j < 8; j++) bufA[j] = __ldcg(hp + (size_t)(kc + 16 + j) * 8);
            }
#pragma unroll
            for (int j = 0; j < 8; j++) {
                float4 hv = bufB[j];
                unsigned long long h0 = dup2(hv.x), h1 = dup2(hv.y);
                unsigned long long h2 = dup2(hv.z), h3 = dup2(hv.w);
                const ulonglong2* wr = wrow0 + (size_t)(kc + 8 + j) * 8;
#pragma unroll
                for (int q = 0; q < 4; q++) {
                    ulonglong2 w2 = wr[q];
                    fma2(acc[0][2 * q], h0, w2.x); fma2(acc[0][2 * q + 1], h0, w2.y);
                    fma2(acc[1][2 * q], h1, w2.x); fma2(acc[1][2 * q + 1], h1, w2.y);
                    fma2(acc[2][2 * q], h2, w2.x); fma2(acc[2][2 * q + 1], h2, w2.y);
                    fma2(acc[3][2 * q], h3, w2.x); fma2(acc[3][2 * q + 1], h3, w2.y);
                }
            }
        }

        // ---- write partials: red[s][cp_global][b], packed STS.128 ----
#pragma unroll
        for (int p = 0; p < 8; p++) {
            ulonglong2 v0, v1;
            v0.x = acc[0][p]; v0.y = acc[1][p];
            v1.x = acc[2][p]; v1.y = acc[3][p];
            unsigned long long* base = &red[((size_t)s * 16 + cg * 8 + p) * 32 + b0];
            *(ulonglong2*)(base) = v0;       // batches b0, b0+1
            *(ulonglong2*)(base + 2) = v1;   // batches b0+2, b0+3
        }
        __syncthreads();

        // ---- reduce + gate math: thread = (unit up, batch gb) ----
        float h_new;
        {
            unsigned long long fiv = 0ull, gov = 0ull;
#pragma unroll
            for (int ss = 0; ss < NSLICE; ss++) {
                add2(fiv, red[((size_t)ss * 16 + 2 * up) * 32 + gb]);
                add2(gov, red[((size_t)ss * 16 + 2 * up + 1) * 32 + gb]);
            }
            float2 fi = unpack2(fiv);
            float2 go = unpack2(gov);
            float zf = fi.x + zx4.x;
            float zi = fi.y + zx4.y;
            float zg = go.x + zx4.z;
            float zo = go.y + zx4.w;

            float f = sigmoidf_(zf);
            float ii = sigmoidf_(zi);
            float g = tanhf_(zg);
            float o = sigmoidf_(zo);
            c_state = f * c_state + ii * g;
            h_new = o * tanhf_(c_state);

            __stcg(&hTo[ug * 32 + gb], h_new);
        }

        // ---- distributed flag barrier ----
        __syncthreads();   // all h stores issued, red consumed
        if (tid == 0) st_release(&g_flags[cu * 32], (unsigned)(t + 1));

        // Overlap with barrier: out[] store (no cross-CTA consumer)
        out[((size_t)gb * TT + t) * UU + ug] = h_new;

        if (tid < NCTA) {
            unsigned target = (unsigned)(t + 1);
            while (ld_acquire(&g_flags[tid * 32]) < target) {}
        }
        __syncthreads();
    }
}

// ===========================================================================
// Launch
// ===========================================================================
extern "C" void kernel_launch(void* const* d_in, const int* in_sizes, int n_in,
                              void* d_out, int out_size) {
    const float* data = (const float*)d_in[0];
    const float* Wf = (const float*)d_in[1];
    const float* bf = (const float*)d_in[2];
    const float* Wi = (const float*)d_in[3];
    const float* bi = (const float*)d_in[4];
    const float* Wc = (const float*)d_in[5];
    const float* bc = (const float*)d_in[6];
    const float* Wo = (const float*)d_in[7];
    const float* bo = (const float*)d_in[8];
    float* out = (float*)d_out;

    prep_kernel<<<512, 256>>>(Wf, Wi, Wc, Wo, bf, bi, bc, bo);

    dim3 zgrid(TT * BB / ZBM, NC / ZBN);
    zx_kernel<<<zgrid, 256>>>(data);

    static int smem_set = 0;
    const int smem_bytes = 1024 * 32 * 4 + NSLICE * 16 * 32 * 8;  // 128KB + 64KB = 192KB
    if (!smem_set) {
        cudaFuncSetAttribute(lstm_persistent,
                             cudaFuncAttributeMaxDynamicSharedMemorySize, smem_bytes);
        smem_set = 1;
    }
    lstm_persistent<<<NCTA, 256, smem_bytes>>>(out);
}

// round 8
// speedup vs baseline: 1.0418x; 1.0006x over previous
#include <cuda_runtime.h>
#include <math.h>
#include <stdint.h>

// Problem constants
#define BB 32
#define TT 512
#define DD 512
#define UU 1024
#define NC 4096   // 4*U packed gate columns, layout [unit][gate], gate order f,i,g,o

#define NCTA 128      // persistent CTAs (1 per SM)
#define CU 32         // gate-cols per CTA (8 units)
#define NSLICE 16     // K-split factor
#define KSL 64        // k per slice (1024/16)

// -------- device scratch --------
__device__ float g_Whp[1024 * 4096];          // [k][u*4+g] recurrent weights (packed)
__device__ float g_Wxp[512 * 4096];           // [d][u*4+g] input weights (packed)
__device__ float g_bp[4096];                  // packed biases
__device__ float g_zx[(size_t)TT * BB * NC];  // [t][b][u*4+g]  x-part (+bias)
__device__ float g_hT[2][UU * BB];            // ping-pong hidden state, layout [u][b]
__device__ unsigned g_flags[NCTA * 32];       // per-CTA step flags (128B apart)

// -------- f32x2 helpers --------
__device__ __forceinline__ void fma2(unsigned long long& acc, unsigned long long a,
                                     unsigned long long b) {
    asm("fma.rn.f32x2 %0, %1, %2, %3;" : "=l"(acc) : "l"(a), "l"(b), "l"(acc));
}
__device__ __forceinline__ void add2(unsigned long long& acc, unsigned long long a) {
    asm("add.rn.f32x2 %0, %1, %2;" : "=l"(acc) : "l"(acc), "l"(a));
}
__device__ __forceinline__ unsigned long long dup2(float x) {
    unsigned long long r;
    asm("mov.b64 %0, {%1, %1};" : "=l"(r) : "f"(x));
    return r;
}
__device__ __forceinline__ float2 unpack2(unsigned long long v) {
    float2 r;
    asm("mov.b64 {%0, %1}, %2;" : "=f"(r.x), "=f"(r.y) : "l"(v));
    return r;
}
__device__ __forceinline__ float sigmoidf_(float x) {
    return 1.0f / (1.0f + __expf(-x));
}
__device__ __forceinline__ float tanhf_(float x) {
    return 1.0f - 2.0f / (__expf(2.0f * x) + 1.0f);
}

// -------- barrier primitives --------
__device__ __forceinline__ void st_release(unsigned* p, unsigned v) {
    asm volatile("st.release.gpu.u32 [%0], %1;" :: "l"(p), "r"(v) : "memory");
}
__device__ __forceinline__ unsigned ld_acquire(unsigned* p) {
    unsigned v;
    asm volatile("ld.acquire.gpu.u32 %0, [%1];" : "=r"(v) : "l"(p) : "memory");
    return v;
}

// ===========================================================================
// Prep: pack weights gate-interleaved, pack biases, zero h0 + flags
// ===========================================================================
__global__ void prep_kernel(const float* __restrict__ Wf, const float* __restrict__ Wi,
                            const float* __restrict__ Wc, const float* __restrict__ Wo,
                            const float* __restrict__ bf, const float* __restrict__ bi,
                            const float* __restrict__ bc, const float* __restrict__ bo) {
    int idx = blockIdx.x * blockDim.x + threadIdx.x;
    int stride = gridDim.x * blockDim.x;
    for (int i = idx; i < NCTA * 32; i += stride) g_flags[i] = 0u;
    for (int i = idx; i < 1024 * 1024; i += stride) {
        int k = i >> 10, u = i & 1023;
        int s = k * 1024 + u;
        float4 v = make_float4(Wf[s], Wi[s], Wc[s], Wo[s]);
        *(float4*)&g_Whp[((size_t)k << 12) + (u << 2)] = v;
    }
    for (int i = idx; i < 512 * 1024; i += stride) {
        int d = i >> 10, u = i & 1023;
        int s = (1024 + d) * 1024 + u;
        float4 v = make_float4(Wf[s], Wi[s], Wc[s], Wo[s]);
        *(float4*)&g_Wxp[((size_t)d << 12) + (u << 2)] = v;
    }
    for (int u = idx; u < 1024; u += stride)
        *(float4*)&g_bp[u << 2] = make_float4(bf[u], bi[u], bc[u], bo[u]);
    for (int i = idx; i < UU * BB; i += stride) g_hT[0][i] = 0.0f;
}

// ===========================================================================
// zx GEMM (unchanged):  zx[t][b][c] = bias[c] + sum_d x[b][t][d] * Wxp[d][c]
// ===========================================================================
#define ZBM 64
#define ZBN 64
#define ZBK 32
#define ZAPAD 68

__global__ __launch_bounds__(256) void zx_kernel(const float* __restrict__ x) {
    __shared__ __align__(16) float As[ZBK][ZAPAD];
    __shared__ __align__(16) float Bs[ZBK][ZBN];

    int row0 = blockIdx.x * ZBM;
    int c0 = blockIdx.y * ZBN;
    int tid = threadIdx.x;
    int tx = tid & 15;
    int ty = tid >> 4;

    unsigned long long acc01[4], acc23[4];
#pragma unroll
    for (int r = 0; r < 4; r++) { acc01[r] = 0ull; acc23[r] = 0ull; }

    int ar = tid >> 2, akq = tid & 3;
    int bkr = tid >> 3, bcq = tid & 7;

    for (int k0 = 0; k0 < DD; k0 += ZBK) {
        __syncthreads();
#pragma unroll
        for (int i = 0; i < 2; i++) {
            int koff = (akq + i * 4) * 4;
            int row = row0 + ar;
            int t = row >> 5, b = row & 31;
            float4 v = *(const float4*)&x[((size_t)b * TT + t) * DD + k0 + koff];
            As[koff + 0][ar] = v.x;
            As[koff + 1][ar] = v.y;
            As[koff + 2][ar] = v.z;
            As[koff + 3][ar] = v.w;
        }
#pragma unroll
        for (int i = 0; i < 2; i++) {
            int coff = (bcq + i * 8) * 4;
            float4 v = *(const float4*)&g_Wxp[(size_t)(k0 + bkr) * NC + c0 + coff];
            *(float4*)&Bs[bkr][coff] = v;
        }
        __syncthreads();

#pragma unroll
        for (int kk = 0; kk < ZBK; kk++) {
            float4 a = *(const float4*)&As[kk][ty * 4];
            ulonglong2 bv = *(const ulonglong2*)&Bs[kk][tx * 4];
            unsigned long long a0 = dup2(a.x);
            unsigned long long a1 = dup2(a.y);
            unsigned long long a2 = dup2(a.z);
            unsigned long long a3 = dup2(a.w);
            fma2(acc01[0], a0, bv.x); fma2(acc23[0], a0, bv.y);
            fma2(acc01[1], a1, bv.x); fma2(acc23[1], a1, bv.y);
            fma2(acc01[2], a2, bv.x); fma2(acc23[2], a2, bv.y);
            fma2(acc01[3], a3, bv.x); fma2(acc23[3], a3, bv.y);
        }
    }

    float4 bias = *(const float4*)&g_bp[c0 + tx * 4];
#pragma unroll
    for (int r = 0; r < 4; r++) {
        float2 v01 = unpack2(acc01[r]);
        float2 v23 = unpack2(acc23[r]);
        float4 o;
        o.x = v01.x + bias.x;
        o.y = v01.y + bias.y;
        o.z = v23.x + bias.z;
        o.w = v23.y + bias.w;
        int row = row0 + ty * 4 + r;
        *(float4*)&g_zx[(size_t)row * NC + c0 + tx * 4] = o;
    }
}

// ===========================================================================
// Persistent recurrent kernel: exact R5 GEMM core (NSLICE=16, 4b x 16c tile,
// float4 h loads, depth-8 prefetch). Tail-only changes vs R5:
//   - distributed flag barrier (st.release + parallel per-flag polls)
//   - STS.128 packed partial stores (16 instead of 32 per thread)
// smem: ws[1024][32] (128KB) + red[16][16][32] ull (64KB) = 192KB
// ===========================================================================
__global__ __launch_bounds__(256, 1) void lstm_persistent(float* __restrict__ out) {
    extern __shared__ __align__(16) float smem[];
    float* ws = smem;                                                   // 128KB
    unsigned long long* red = (unsigned long long*)(smem + 1024 * 32);  // 64KB

    const int tid = threadIdx.x;
    const int cu = blockIdx.x;

    // --- load this CTA's weight slice into smem (once) ---
    {
        const float4* src = (const float4*)(g_Whp + (size_t)cu * CU);
        float4* dst = (float4*)ws;
        for (int i = tid; i < 1024 * 8; i += 256) {
            int k = i >> 3, q = i & 7;
            dst[k * 8 + q] = src[(size_t)k * 1024 + q];
        }
    }

    // --- GEMM roles (R5) ---
    const int s = tid >> 4;          // k-slice 0..15
    const int cov = tid & 15;
    const int bg = cov & 7;          // batch group (4 batches)
    const int cg = cov >> 3;         // col group (16 cols)
    const int b0 = bg * 4;
    const int c0 = cg * 16;
    const int kb = s * KSL;

    // --- gate-math roles ---
    const int up = tid >> 5;         // unit-in-CTA 0..7
    const int gb = tid & 31;         // batch 0..31
    const int ug = cu * 8 + up;      // global unit

    float c_state = 0.0f;

    __syncthreads();                 // weights ready

    for (int t = 0; t < TT; t++) {
        const float* __restrict__ hT = g_hT[t & 1];
        float* __restrict__ hTo = g_hT[(t + 1) & 1];

        // Prefetch zx for this step (hidden behind the GEMM)
        float4 zx4 = __ldcg((const float4*)&g_zx[((size_t)t * BB + gb) * NC + ug * 4]);

        // ---- GEMM: acc[b][cp] over k in [kb, kb+64) ----
        unsigned long long acc[4][8];
#pragma unroll
        for (int b = 0; b < 4; b++)
#pragma unroll
            for (int p = 0; p < 8; p++) acc[b][p] = 0ull;

        const float4* hp = (const float4*)(hT + (size_t)kb * 32 + b0);
        const ulonglong2* wrow0 = (const ulonglong2*)(ws + kb * 32 + c0);

        // Deep double-buffer: 8 k-iters per buffer
        float4 bufA[8], bufB[8];
#pragma unroll
        for (int j = 0; j < 8; j++) bufA[j] = __ldcg(hp + (size_t)j * 8);

#pragma unroll
        for (int kc = 0; kc < KSL; kc += 16) {
#pragma unroll
            for (int j = 0; j < 8; j++) bufB[j] = __ldcg(hp + (size_t)(kc + 8 + j) * 8);
#pragma unroll
            for (int j = 0; j < 8; j++) {
                float4 hv = bufA[j];
                unsigned long long h0 = dup2(hv.x), h1 = dup2(hv.y);
                unsigned long long h2 = dup2(hv.z), h3 = dup2(hv.w);
                const ulonglong2* wr = wrow0 + (size_t)(kc + j) * 8;
#pragma unroll
                for (int q = 0; q < 4; q++) {
                    ulonglong2 w2 = wr[q];
                    fma2(acc[0][2 * q], h0, w2.x); fma2(acc[0][2 * q + 1], h0, w2.y);
                    fma2(acc[1][2 * q], h1, w2.x); fma2(acc[1][2 * q + 1], h1, w2.y);
                    fma2(acc[2][2 * q], h2, w2.x); fma2(acc[2][2 * q + 1], h2, w2.y);
                    fma2(acc[3][2 * q], h3, w2.x); fma2(acc[3][2 * q + 1], h3, w2.y);
                }
            }
            if (kc + 16 < KSL) {
#pragma unroll
                for (int j = 0; j < 8; j++) bufA[j] = __ldcg(hp + (size_t)(kc + 16 + j) * 8);
            }
#pragma unroll
            for (int j = 0; j < 8; j++) {
                float4 hv = bufB[j];
                unsigned long long h0 = dup2(hv.x), h1 = dup2(hv.y);
                unsigned long long h2 = dup2(hv.z), h3 = dup2(hv.w);
                const ulonglong2* wr = wrow0 + (size_t)(kc + 8 + j) * 8;
#pragma unroll
                for (int q = 0; q < 4; q++) {
                    ulonglong2 w2 = wr[q];
                    fma2(acc[0][2 * q], h0, w2.x); fma2(acc[0][2 * q + 1], h0, w2.y);
                    fma2(acc[1][2 * q], h1, w2.x); fma2(acc[1][2 * q + 1], h1, w2.y);
                    fma2(acc[2][2 * q], h2, w2.x); fma2(acc[2][2 * q + 1], h2, w2.y);
                    fma2(acc[3][2 * q], h3, w2.x); fma2(acc[3][2 * q + 1], h3, w2.y);
                }
            }
        }

        // ---- write partials: red[s][cp_global][b], packed STS.128 ----
#pragma unroll
        for (int p = 0; p < 8; p++) {
            ulonglong2 v0, v1;
            v0.x = acc[0][p]; v0.y = acc[1][p];
            v1.x = acc[2][p]; v1.y = acc[3][p];
            unsigned long long* base = &red[((size_t)s * 16 + cg * 8 + p) * 32 + b0];
            *(ulonglong2*)(base) = v0;       // batches b0, b0+1
            *(ulonglong2*)(base + 2) = v1;   // batches b0+2, b0+3
        }
        __syncthreads();

        // ---- reduce + gate math: thread = (unit up, batch gb) ----
        float h_new;
        {
            unsigned long long fiv = 0ull, gov = 0ull;
#pragma unroll
            for (int ss = 0; ss < NSLICE; ss++) {
                add2(fiv, red[((size_t)ss * 16 + 2 * up) * 32 + gb]);
                add2(gov, red[((size_t)ss * 16 + 2 * up + 1) * 32 + gb]);
            }
            float2 fi = unpack2(fiv);
            float2 go = unpack2(gov);
            float zf = fi.x + zx4.x;
            float zi = fi.y + zx4.y;
            float zg = go.x + zx4.z;
            float zo = go.y + zx4.w;

            float f = sigmoidf_(zf);
            float ii = sigmoidf_(zi);
            float g = tanhf_(zg);
            float o = sigmoidf_(zo);
            c_state = f * c_state + ii * g;
            h_new = o * tanhf_(c_state);

            __stcg(&hTo[ug * 32 + gb], h_new);
        }

        // ---- distributed flag barrier ----
        __syncthreads();   // all h stores issued, red consumed
        if (tid == 0) st_release(&g_flags[cu * 32], (unsigned)(t + 1));

        // Overlap with barrier: out[] store (no cross-CTA consumer)
        out[((size_t)gb * TT + t) * UU + ug] = h_new;

        if (tid < NCTA) {
            unsigned target = (unsigned)(t + 1);
            while (ld_acquire(&g_flags[tid * 32]) < target) {}
        }
        __syncthreads();
    }
}

// ===========================================================================
// Launch
// ===========================================================================
extern "C" void kernel_launch(void* const* d_in, const int* in_sizes, int n_in,
                              void* d_out, int out_size) {
    const float* data = (const float*)d_in[0];
    const float* Wf = (const float*)d_in[1];
    const float* bf = (const float*)d_in[2];
    const float* Wi = (const float*)d_in[3];
    const float* bi = (const float*)d_in[4];
    const float* Wc = (const float*)d_in[5];
    const float* bc = (const float*)d_in[6];
    const float* Wo = (const float*)d_in[7];
    const float* bo = (const float*)d_in[8];
    float* out = (float*)d_out;

    prep_kernel<<<512, 256>>>(Wf, Wi, Wc, Wo, bf, bi, bc, bo);

    dim3 zgrid(TT * BB / ZBM, NC / ZBN);
    zx_kernel<<<zgrid, 256>>>(data);

    static int smem_set = 0;
    const int smem_bytes = 1024 * 32 * 4 + NSLICE * 16 * 32 * 8;  // 128KB + 64KB = 192KB
    if (!smem_set) {
        cudaFuncSetAttribute(lstm_persistent,
                             cudaFuncAttributeMaxDynamicSharedMemorySize, smem_bytes);
        smem_set = 1;
    }
    lstm_persistent<<<NCTA, 256, smem_bytes>>>(out);
}

// round 10
// speedup vs baseline: 1.2568x; 1.2064x over previous
#include <cuda_runtime.h>
#include <cuda_bf16.h>
#include <math.h>
#include <stdint.h>

// Problem constants
#define BB 32
#define TT 512
#define DD 512
#define UU 1024
#define NC 4096   // 4*U packed gate columns, layout [unit][gate], gate order f,i,g,o

#define NCTA 128      // persistent CTAs (1 per SM)
#define CU 32         // gate-cols per CTA (8 units)
#define NSLICE 16     // K-split factor
#define KSL 64        // k per slice (1024/16)

// -------- device scratch --------
__device__ float g_Whp[1024 * 4096];          // [k][u*4+g] recurrent weights (packed fp32)
__device__ float g_bp[4096];                  // packed biases
__device__ float g_zx[(size_t)TT * BB * NC];  // [t][b][u*4+g]  x-part (+bias)
__device__ float g_hT[2][UU * BB];            // ping-pong hidden state, layout [u][b]
__device__ unsigned g_bar;                    // grid barrier counter
// bf16 hi/lo decompositions for tensor-core zx
__device__ __nv_bfloat16 g_xhi[(size_t)TT * BB * DD];  // A: [row=t*32+b][d]
__device__ __nv_bfloat16 g_xlo[(size_t)TT * BB * DD];
__device__ __nv_bfloat16 g_bwhi[(size_t)NC * DD];      // B: [c=gate col][d]
__device__ __nv_bfloat16 g_bwlo[(size_t)NC * DD];

// -------- f32x2 helpers --------
__device__ __forceinline__ void fma2(unsigned long long& acc, unsigned long long a,
                                     unsigned long long b) {
    asm("fma.rn.f32x2 %0, %1, %2, %3;" : "=l"(acc) : "l"(a), "l"(b), "l"(acc));
}
__device__ __forceinline__ void add2(unsigned long long& acc, unsigned long long a) {
    asm("add.rn.f32x2 %0, %1, %2;" : "=l"(acc) : "l"(acc), "l"(a));
}
__device__ __forceinline__ unsigned long long dup2(float x) {
    unsigned long long r;
    asm("mov.b64 %0, {%1, %1};" : "=l"(r) : "f"(x));
    return r;
}
__device__ __forceinline__ float2 unpack2(unsigned long long v) {
    float2 r;
    asm("mov.b64 {%0, %1}, %2;" : "=f"(r.x), "=f"(r.y) : "l"(v));
    return r;
}
__device__ __forceinline__ float sigmoidf_(float x) {
    return 1.0f / (1.0f + __expf(-x));
}
__device__ __forceinline__ float tanhf_(float x) {
    return 1.0f - 2.0f / (__expf(2.0f * x) + 1.0f);
}

// -------- barrier primitives --------
__device__ __forceinline__ void bar_arrive_release(unsigned* p) {
    unsigned old;
    asm volatile("atom.add.release.gpu.u32 %0, [%1], 1;" : "=r"(old) : "l"(p) : "memory");
}
__device__ __forceinline__ unsigned ld_acquire(unsigned* p) {
    unsigned v;
    asm volatile("ld.acquire.gpu.u32 %0, [%1];" : "=r"(v) : "l"(p) : "memory");
    return v;
}

// -------- mma.sync bf16 (sm_80+ baseline; works on plain sm_103 target) ----
__device__ __forceinline__ void mma16816(float* c, const uint32_t* a, const uint32_t* b) {
    asm volatile(
        "mma.sync.aligned.m16n8k16.row.col.f32.bf16.bf16.f32 "
        "{%0,%1,%2,%3}, {%4,%5,%6,%7}, {%8,%9}, {%0,%1,%2,%3};"
        : "+f"(c[0]), "+f"(c[1]), "+f"(c[2]), "+f"(c[3])
        : "r"(a[0]), "r"(a[1]), "r"(a[2]), "r"(a[3]), "r"(b[0]), "r"(b[1]));
}

// ===========================================================================
// Prep: pack recurrent weights, biases, zero h0/bar, bf16 hi/lo input weights
// ===========================================================================
__global__ void prep_kernel(const float* __restrict__ Wf, const float* __restrict__ Wi,
                            const float* __restrict__ Wc, const float* __restrict__ Wo,
                            const float* __restrict__ bf, const float* __restrict__ bi,
                            const float* __restrict__ bc, const float* __restrict__ bo) {
    int idx = blockIdx.x * blockDim.x + threadIdx.x;
    int stride = gridDim.x * blockDim.x;
    if (idx == 0) g_bar = 0u;
    for (int i = idx; i < 1024 * 1024; i += stride) {
        int k = i >> 10, u = i & 1023;
        int s = k * 1024 + u;
        float4 v = make_float4(Wf[s], Wi[s], Wc[s], Wo[s]);
        *(float4*)&g_Whp[((size_t)k << 12) + (u << 2)] = v;
    }
    // Input weights -> bf16 hi/lo, layout [c][d]
    for (int i = idx; i < 512 * 1024; i += stride) {
        int d = i >> 10, u = i & 1023;
        int s = (1024 + d) * 1024 + u;
        float vv[4] = {Wf[s], Wi[s], Wc[s], Wo[s]};
#pragma unroll
        for (int g = 0; g < 4; g++) {
            int c = u * 4 + g;
            __nv_bfloat16 h = __float2bfloat16(vv[g]);
            g_bwhi[(size_t)c * 512 + d] = h;
            g_bwlo[(size_t)c * 512 + d] = __float2bfloat16(vv[g] - __bfloat162float(h));
        }
    }
    for (int u = idx; u < 1024; u += stride)
        *(float4*)&g_bp[u << 2] = make_float4(bf[u], bi[u], bc[u], bo[u]);
    for (int i = idx; i < UU * BB; i += stride) g_hT[0][i] = 0.0f;
}

// ===========================================================================
// Convert x -> bf16 hi/lo, layout [row=t*32+b][d]
// ===========================================================================
__global__ void conv_x_kernel(const float* __restrict__ x) {
    int idx = blockIdx.x * blockDim.x + threadIdx.x;
    int stride = gridDim.x * blockDim.x;
    const int N4 = BB * TT * DD / 4;
    for (int i = idx; i < N4; i += stride) {
        int d4 = i & 127;
        int rt = i >> 7;           // b*512 + t
        int b = rt >> 9, t = rt & 511;
        float4 v = *(const float4*)&x[(size_t)i * 4];
        size_t o = ((size_t)(t * 32 + b)) * 512 + d4 * 4;

        __nv_bfloat16 h0 = __float2bfloat16(v.x);
        __nv_bfloat16 h1 = __float2bfloat16(v.y);
        __nv_bfloat16 h2 = __float2bfloat16(v.z);
        __nv_bfloat16 h3 = __float2bfloat16(v.w);
        __nv_bfloat162 hp0; hp0.x = h0; hp0.y = h1;
        __nv_bfloat162 hp1; hp1.x = h2; hp1.y = h3;
        *(__nv_bfloat162*)(g_xhi + o) = hp0;
        *(__nv_bfloat162*)(g_xhi + o + 2) = hp1;

        __nv_bfloat162 lp0, lp1;
        lp0.x = __float2bfloat16(v.x - __bfloat162float(h0));
        lp0.y = __float2bfloat16(v.y - __bfloat162float(h1));
        lp1.x = __float2bfloat16(v.z - __bfloat162float(h2));
        lp1.y = __float2bfloat16(v.w - __bfloat162float(h3));
        *(__nv_bfloat162*)(g_xlo + o) = lp0;
        *(__nv_bfloat162*)(g_xlo + o + 2) = lp1;
    }
}

// ===========================================================================
// zx GEMM via mma.sync (bf16x3): zx[row][c] = bias[c] + x[row][:] . W[:][c]
// CTA tile 128(m) x 64(n), K chunks of 32. 8 warps: wm = wid>>1, wn = wid&1;
// warp tile 32x32 = 2 m-frags x 4 n-frags of m16n8k16.
// A/B staged in smem with 80B row stride (bank-clean fragment loads).
// D += Ahi*Bhi + Ahi*Blo + Alo*Bhi  (fp32 accum)
// ===========================================================================
#define ZMT 128
#define ZNT 64
#define ZKC 32
#define ZST 40    // smem row stride in bf16 units (80 bytes)

__global__ __launch_bounds__(256) void zx_mma_kernel() {
    __shared__ __align__(16) __nv_bfloat16 sAhi[ZMT * ZST];
    __shared__ __align__(16) __nv_bfloat16 sAlo[ZMT * ZST];
    __shared__ __align__(16) __nv_bfloat16 sBhi[ZNT * ZST];
    __shared__ __align__(16) __nv_bfloat16 sBlo[ZNT * ZST];

    const int tid = threadIdx.x;
    const int lane = tid & 31;
    const int wid = tid >> 5;
    const int wm = wid >> 1;     // 0..3
    const int wn = wid & 1;      // 0..1
    const int gr = lane >> 2;    // 0..7
    const int tg = lane & 3;     // 0..3
    const int n0 = blockIdx.x * ZNT;
    const int row0 = blockIdx.y * ZMT;

    float c[2][4][4];
#pragma unroll
    for (int mi = 0; mi < 2; mi++)
#pragma unroll
        for (int ni = 0; ni < 4; ni++)
#pragma unroll
            for (int r = 0; r < 4; r++) c[mi][ni][r] = 0.0f;

    for (int kc = 0; kc < DD / ZKC; kc++) {
        __syncthreads();   // previous chunk's fragment loads complete
        // ---- stage A: 128 rows x 32 cols, tasks (row, q of 8 cols) ----
#pragma unroll
        for (int it = 0; it < 2; it++) {
            int idx = tid + it * 256;
            int r = idx >> 2, q = idx & 3;
            size_t go = ((size_t)(row0 + r)) * 512 + kc * 32 + q * 8;
            *(uint4*)&sAhi[r * ZST + q * 8] = *(const uint4*)(g_xhi + go);
            *(uint4*)&sAlo[r * ZST + q * 8] = *(const uint4*)(g_xlo + go);
        }
        // ---- stage B: 64 rows x 32 cols ----
        {
            int r = tid >> 2, q = tid & 3;
            size_t go = ((size_t)(n0 + r)) * 512 + kc * 32 + q * 8;
            *(uint4*)&sBhi[r * ZST + q * 8] = *(const uint4*)(g_bwhi + go);
            *(uint4*)&sBlo[r * ZST + q * 8] = *(const uint4*)(g_bwlo + go);
        }
        __syncthreads();

#pragma unroll
        for (int ks = 0; ks < 2; ks++) {
            // A fragments
            uint32_t ahi[2][4], alo[2][4];
#pragma unroll
            for (int mi = 0; mi < 2; mi++) {
                int rb = (wm * 32 + mi * 16 + gr) * ZST + ks * 16 + tg * 2;
                ahi[mi][0] = *(const uint32_t*)&sAhi[rb];
                ahi[mi][1] = *(const uint32_t*)&sAhi[rb + 8 * ZST];
                ahi[mi][2] = *(const uint32_t*)&sAhi[rb + 8];
                ahi[mi][3] = *(const uint32_t*)&sAhi[rb + 8 * ZST + 8];
                alo[mi][0] = *(const uint32_t*)&sAlo[rb];
                alo[mi][1] = *(const uint32_t*)&sAlo[rb + 8 * ZST];
                alo[mi][2] = *(const uint32_t*)&sAlo[rb + 8];
                alo[mi][3] = *(const uint32_t*)&sAlo[rb + 8 * ZST + 8];
            }
            // B fragments
            uint32_t bhi[4][2], blo[4][2];
#pragma unroll
            for (int ni = 0; ni < 4; ni++) {
                int rb = (wn * 32 + ni * 8 + gr) * ZST + ks * 16 + tg * 2;
                bhi[ni][0] = *(const uint32_t*)&sBhi[rb];
                bhi[ni][1] = *(const uint32_t*)&sBhi[rb + 8];
                blo[ni][0] = *(const uint32_t*)&sBlo[rb];
                blo[ni][1] = *(const uint32_t*)&sBlo[rb + 8];
            }
#pragma unroll
            for (int mi = 0; mi < 2; mi++)
#pragma unroll
                for (int ni = 0; ni < 4; ni++) {
                    mma16816(c[mi][ni], ahi[mi], bhi[ni]);
                    mma16816(c[mi][ni], ahi[mi], blo[ni]);
                    mma16816(c[mi][ni], alo[mi], bhi[ni]);
                }
        }
    }

    // ---- epilogue: + bias, store ----
    const int rbase = row0 + wm * 32;
    const int cbase = n0 + wn * 32;
#pragma unroll
    for (int mi = 0; mi < 2; mi++) {
#pragma unroll
        for (int ni = 0; ni < 4; ni++) {
            int r = rbase + mi * 16 + gr;
            int col = cbase + ni * 8 + tg * 2;
            float2 b01 = *(const float2*)&g_bp[col];
            float2 v0 = make_float2(c[mi][ni][0] + b01.x, c[mi][ni][1] + b01.y);
            float2 v1 = make_float2(c[mi][ni][2] + b01.x, c[mi][ni][3] + b01.y);
            *(float2*)&g_zx[(size_t)r * NC + col] = v0;
            *(float2*)&g_zx[(size_t)(r + 8) * NC + col] = v1;
        }
    }
}

// ===========================================================================
// Persistent recurrent kernel — EXACT R5 (best measured: 5397.6us)
// smem: ws[1024][32] (128KB) + red[16][16][32] ull (64KB) = 192KB
// ===========================================================================
__global__ __launch_bounds__(256, 1) void lstm_persistent(float* __restrict__ out) {
    extern __shared__ __align__(16) float psmem[];
    float* ws = psmem;                                                   // 128KB
    unsigned long long* red = (unsigned long long*)(psmem + 1024 * 32);  // 64KB

    const int tid = threadIdx.x;
    const int cu = blockIdx.x;

    {
        const float4* src = (const float4*)(g_Whp + (size_t)cu * CU);
        float4* dst = (float4*)ws;
        for (int i = tid; i < 1024 * 8; i += 256) {
            int k = i >> 3, q = i & 7;
            dst[k * 8 + q] = src[(size_t)k * 1024 + q];
        }
    }

    const int s = tid >> 4;
    const int cov = tid & 15;
    const int bg = cov & 7;
    const int cg = cov >> 3;
    const int b0 = bg * 4;
    const int c0 = cg * 16;
    const int kb = s * KSL;

    const int up = tid >> 5;
    const int gb = tid & 31;
    const int ug = cu * 8 + up;

    float c_state = 0.0f;

    __syncthreads();

    for (int t = 0; t < TT; t++) {
        const float* __restrict__ hT = g_hT[t & 1];
        float* __restrict__ hTo = g_hT[(t + 1) & 1];

        float4 zx4 = __ldcg((const float4*)&g_zx[((size_t)t * BB + gb) * NC + ug * 4]);

        unsigned long long acc[4][8];
#pragma unroll
        for (int b = 0; b < 4; b++)
#pragma unroll
            for (int p = 0; p < 8; p++) acc[b][p] = 0ull;

        const float4* hp = (const float4*)(hT + (size_t)kb * 32 + b0);
        const ulonglong2* wrow0 = (const ulonglong2*)(ws + kb * 32 + c0);

        float4 bufA[8], bufB[8];
#pragma unroll
        for (int j = 0; j < 8; j++) bufA[j] = __ldcg(hp + (size_t)j * 8);

#pragma unroll
        for (int kc = 0; kc < KSL; kc += 16) {
#pragma unroll
            for (int j = 0; j < 8; j++) bufB[j] = __ldcg(hp + (size_t)(kc + 8 + j) * 8);
#pragma unroll
            for (int j = 0; j < 8; j++) {
                float4 hv = bufA[j];
                unsigned long long h0 = dup2(hv.x), h1 = dup2(hv.y);
                unsigned long long h2 = dup2(hv.z), h3 = dup2(hv.w);
                const ulonglong2* wr = wrow0 + (size_t)(kc + j) * 8;
#pragma unroll
                for (int q = 0; q < 4; q++) {
                    ulonglong2 w2 = wr[q];
                    fma2(acc[0][2 * q], h0, w2.x); fma2(acc[0][2 * q + 1], h0, w2.y);
                    fma2(acc[1][2 * q], h1, w2.x); fma2(acc[1][2 * q + 1], h1, w2.y);
                    fma2(acc[2][2 * q], h2, w2.x); fma2(acc[2][2 * q + 1], h2, w2.y);
                    fma2(acc[3][2 * q], h3, w2.x); fma2(acc[3][2 * q + 1], h3, w2.y);
                }
            }
            if (kc + 16 < KSL) {
#pragma unroll
                for (int j = 0; j < 8; j++) bufA[j] = __ldcg(hp + (size_t)(kc + 16 + j) * 8);
            }
#pragma unroll
            for (int j = 0; j < 8; j++) {
                float4 hv = bufB[j];
                unsigned long long h0 = dup2(hv.x), h1 = dup2(hv.y);
                unsigned long long h2 = dup2(hv.z), h3 = dup2(hv.w);
                const ulonglong2* wr = wrow0 + (size_t)(kc + 8 + j) * 8;
#pragma unroll
                for (int q = 0; q < 4; q++) {
                    ulonglong2 w2 = wr[q];
                    fma2(acc[0][2 * q], h0, w2.x); fma2(acc[0][2 * q + 1], h0, w2.y);
                    fma2(acc[1][2 * q], h1, w2.x); fma2(acc[1][2 * q + 1], h1, w2.y);
                    fma2(acc[2][2 * q], h2, w2.x); fma2(acc[2][2 * q + 1], h2, w2.y);
                    fma2(acc[3][2 * q], h3, w2.x); fma2(acc[3][2 * q + 1], h3, w2.y);
                }
            }
        }

#pragma unroll
        for (int b = 0; b < 4; b++)
#pragma unroll
            for (int p = 0; p < 8; p++)
                red[((size_t)s * 16 + cg * 8 + p) * 32 + b0 + b] = acc[b][p];
        __syncthreads();

        float h_new;
        {
            unsigned long long fiv = 0ull, gov = 0ull;
#pragma unroll
            for (int ss = 0; ss < NSLICE; ss++) {
                add2(fiv, red[((size_t)ss * 16 + 2 * up) * 32 + gb]);
                add2(gov, red[((size_t)ss * 16 + 2 * up + 1) * 32 + gb]);
            }
            float2 fi = unpack2(fiv);
            float2 go = unpack2(gov);
            float zf = fi.x + zx4.x;
            float zi = fi.y + zx4.y;
            float zg = go.x + zx4.z;
            float zo = go.y + zx4.w;

            float f = sigmoidf_(zf);
            float ii = sigmoidf_(zi);
            float g = tanhf_(zg);
            float o = sigmoidf_(zo);
            c_state = f * c_state + ii * g;
            h_new = o * tanhf_(c_state);

            __stcg(&hTo[ug * 32 + gb], h_new);
        }

        __syncthreads();
        if (tid == 0) bar_arrive_release(&g_bar);

        out[((size_t)gb * TT + t) * UU + ug] = h_new;

        if (tid == 0) {
            unsigned target = (unsigned)NCTA * (unsigned)(t + 1);
            while (ld_acquire(&g_bar) < target) {}
        }
        __syncthreads();
    }
}

// ===========================================================================
// Launch
// ===========================================================================
extern "C" void kernel_launch(void* const* d_in, const int* in_sizes, int n_in,
                              void* d_out, int out_size) {
    const float* data = (const float*)d_in[0];
    const float* Wf = (const float*)d_in[1];
    const float* bf = (const float*)d_in[2];
    const float* Wi = (const float*)d_in[3];
    const float* bi = (const float*)d_in[4];
    const float* Wc = (const float*)d_in[5];
    const float* bc = (const float*)d_in[6];
    const float* Wo = (const float*)d_in[7];
    const float* bo = (const float*)d_in[8];
    float* out = (float*)d_out;

    static int attr_set = 0;
    const int psmem_bytes = 1024 * 32 * 4 + NSLICE * 16 * 32 * 8;  // 192KB
    if (!attr_set) {
        cudaFuncSetAttribute(lstm_persistent,
                             cudaFuncAttributeMaxDynamicSharedMemorySize, psmem_bytes);
        attr_set = 1;
    }

    prep_kernel<<<512, 256>>>(Wf, Wi, Wc, Wo, bf, bi, bc, bo);
    conv_x_kernel<<<2048, 256>>>(data);

    dim3 zgrid(NC / ZNT, (TT * BB) / ZMT);  // (64, 128); x fastest -> A tile reuse in L2
    zx_mma_kernel<<<zgrid, 256>>>();

    lstm_persistent<<<NCTA, 256, psmem_bytes>>>(out);
}

// round 11
// speedup vs baseline: 1.4116x; 1.1232x over previous
#include <cuda_runtime.h>
#include <cuda_bf16.h>
#include <math.h>
#include <stdint.h>

// Problem constants
#define BB 32
#define TT 512
#define DD 512
#define UU 1024
#define NC 4096   // 4*U packed gate columns, layout [unit][gate], gate order f,i,g,o

#define NCTA 128      // persistent CTAs (1 per SM)
#define RPITCH 1048   // smem weight row pitch in bf16 elems (bank-conflict-free)

// -------- device scratch --------
__device__ float g_bp[4096];                  // packed biases
__device__ float g_zx[(size_t)TT * BB * NC];  // [t][b][u*4+g]  x-part (+bias)
__device__ unsigned g_bar;                    // grid barrier counter
// bf16 hi/lo for tensor-core zx
__device__ __nv_bfloat16 g_xhi[(size_t)TT * BB * DD];  // [row=t*32+b][d]
__device__ __nv_bfloat16 g_xlo[(size_t)TT * BB * DD];
__device__ __nv_bfloat16 g_bwhi[(size_t)NC * DD];      // input W  [c][d]
__device__ __nv_bfloat16 g_bwlo[(size_t)NC * DD];
// bf16 hi/lo recurrent weights [c][k]
__device__ __nv_bfloat16 g_rwhi[(size_t)NC * UU];
__device__ __nv_bfloat16 g_rwlo[(size_t)NC * UU];
// bf16 hi/lo hidden state, ping-pong, layout [b][u-swizzled]
__device__ __nv_bfloat16 g_hhi[2][BB * UU];
__device__ __nv_bfloat16 g_hlo[2][BB * UU];

__device__ __forceinline__ float sigmoidf_(float x) {
    return 1.0f / (1.0f + __expf(-x));
}
__device__ __forceinline__ float tanhf_(float x) {
    return 1.0f - 2.0f / (__expf(2.0f * x) + 1.0f);
}

// -------- barrier primitives --------
__device__ __forceinline__ void bar_arrive_release(unsigned* p) {
    unsigned old;
    asm volatile("atom.add.release.gpu.u32 %0, [%1], 1;" : "=r"(old) : "l"(p) : "memory");
}
__device__ __forceinline__ unsigned ld_acquire(unsigned* p) {
    unsigned v;
    asm volatile("ld.acquire.gpu.u32 %0, [%1];" : "=r"(v) : "l"(p) : "memory");
    return v;
}

// -------- mma.sync bf16 (proven on this toolchain in R10) --------
__device__ __forceinline__ void mma16816(float* c, const uint32_t* a, const uint32_t* b) {
    asm volatile(
        "mma.sync.aligned.m16n8k16.row.col.f32.bf16.bf16.f32 "
        "{%0,%1,%2,%3}, {%4,%5,%6,%7}, {%8,%9}, {%0,%1,%2,%3};"
        : "+f"(c[0]), "+f"(c[1]), "+f"(c[2]), "+f"(c[3])
        : "r"(a[0]), "r"(a[1]), "r"(a[2]), "r"(a[3]), "r"(b[0]), "r"(b[1]));
}

// fragment-swizzle: value index i (0..15) -> storage position within 16-tile
__device__ __forceinline__ int fragpos(int i) {
    return (i & 1) + ((i >> 3) << 1) + (i & 6) * 2;
}

// ===========================================================================
// Prep: biases, bf16 hi/lo input + recurrent weights, zero h0 + bar
// ===========================================================================
__global__ void prep_kernel(const float* __restrict__ Wf, const float* __restrict__ Wi,
                            const float* __restrict__ Wc, const float* __restrict__ Wo,
                            const float* __restrict__ bf, const float* __restrict__ bi,
                            const float* __restrict__ bc, const float* __restrict__ bo) {
    int idx = blockIdx.x * blockDim.x + threadIdx.x;
    int stride = gridDim.x * blockDim.x;
    if (idx == 0) g_bar = 0u;
    const float* Ws[4] = {Wf, Wi, Wc, Wo};

    // Input weights -> bf16 hi/lo, layout [c][d]
    for (int i = idx; i < 512 * 1024; i += stride) {
        int d = i >> 10, u = i & 1023;
        int s = (1024 + d) * 1024 + u;
#pragma unroll
        for (int g = 0; g < 4; g++) {
            float v = Ws[g][s];
            int c = u * 4 + g;
            __nv_bfloat16 h = __float2bfloat16(v);
            g_bwhi[(size_t)c * 512 + d] = h;
            g_bwlo[(size_t)c * 512 + d] = __float2bfloat16(v - __bfloat162float(h));
        }
    }
    // Recurrent weights -> bf16 hi/lo, layout [c][k]
    for (size_t i = idx; i < (size_t)NC * UU; i += stride) {
        int c = (int)(i >> 10), k = (int)(i & 1023);
        int u = c >> 2, g = c & 3;
        float v = Ws[g][(size_t)k * 1024 + u];
        __nv_bfloat16 h = __float2bfloat16(v);
        g_rwhi[i] = h;
        g_rwlo[i] = __float2bfloat16(v - __bfloat162float(h));
    }
    for (int u = idx; u < 1024; u += stride)
        *(float4*)&g_bp[u << 2] = make_float4(bf[u], bi[u], bc[u], bo[u]);
    for (int i = idx; i < BB * UU; i += stride) {
        g_hhi[0][i] = __float2bfloat16(0.0f);
        g_hlo[0][i] = __float2bfloat16(0.0f);
    }
}

// ===========================================================================
// Convert x -> bf16 hi/lo, layout [row=t*32+b][d]
// ===========================================================================
__global__ void conv_x_kernel(const float* __restrict__ x) {
    int idx = blockIdx.x * blockDim.x + threadIdx.x;
    int stride = gridDim.x * blockDim.x;
    const int N4 = BB * TT * DD / 4;
    for (int i = idx; i < N4; i += stride) {
        int d4 = i & 127;
        int rt = i >> 7;           // b*512 + t
        int b = rt >> 9, t = rt & 511;
        float4 v = *(const float4*)&x[(size_t)i * 4];
        size_t o = ((size_t)(t * 32 + b)) * 512 + d4 * 4;

        __nv_bfloat16 h0 = __float2bfloat16(v.x);
        __nv_bfloat16 h1 = __float2bfloat16(v.y);
        __nv_bfloat16 h2 = __float2bfloat16(v.z);
        __nv_bfloat16 h3 = __float2bfloat16(v.w);
        __nv_bfloat162 hp0; hp0.x = h0; hp0.y = h1;
        __nv_bfloat162 hp1; hp1.x = h2; hp1.y = h3;
        *(__nv_bfloat162*)(g_xhi + o) = hp0;
        *(__nv_bfloat162*)(g_xhi + o + 2) = hp1;

        __nv_bfloat162 lp0, lp1;
        lp0.x = __float2bfloat16(v.x - __bfloat162float(h0));
        lp0.y = __float2bfloat16(v.y - __bfloat162float(h1));
        lp1.x = __float2bfloat16(v.z - __bfloat162float(h2));
        lp1.y = __float2bfloat16(v.w - __bfloat162float(h3));
        *(__nv_bfloat162*)(g_xlo + o) = lp0;
        *(__nv_bfloat162*)(g_xlo + o + 2) = lp1;
    }
}

// ===========================================================================
// zx GEMM via mma.sync (unchanged from R10 win)
// ===========================================================================
#define ZMT 128
#define ZNT 64
#define ZKC 32
#define ZST 40

__global__ __launch_bounds__(256) void zx_mma_kernel() {
    __shared__ __align__(16) __nv_bfloat16 sAhi[ZMT * ZST];
    __shared__ __align__(16) __nv_bfloat16 sAlo[ZMT * ZST];
    __shared__ __align__(16) __nv_bfloat16 sBhi[ZNT * ZST];
    __shared__ __align__(16) __nv_bfloat16 sBlo[ZNT * ZST];

    const int tid = threadIdx.x;
    const int lane = tid & 31;
    const int wid = tid >> 5;
    const int wm = wid >> 1;
    const int wn = wid & 1;
    const int gr = lane >> 2;
    const int tg = lane & 3;
    const int n0 = blockIdx.x * ZNT;
    const int row0 = blockIdx.y * ZMT;

    float c[2][4][4];
#pragma unroll
    for (int mi = 0; mi < 2; mi++)
#pragma unroll
        for (int ni = 0; ni < 4; ni++)
#pragma unroll
            for (int r = 0; r < 4; r++) c[mi][ni][r] = 0.0f;

    for (int kc = 0; kc < DD / ZKC; kc++) {
        __syncthreads();
#pragma unroll
        for (int it = 0; it < 2; it++) {
            int idx = tid + it * 256;
            int r = idx >> 2, q = idx & 3;
            size_t go = ((size_t)(row0 + r)) * 512 + kc * 32 + q * 8;
            *(uint4*)&sAhi[r * ZST + q * 8] = *(const uint4*)(g_xhi + go);
            *(uint4*)&sAlo[r * ZST + q * 8] = *(const uint4*)(g_xlo + go);
        }
        {
            int r = tid >> 2, q = tid & 3;
            size_t go = ((size_t)(n0 + r)) * 512 + kc * 32 + q * 8;
            *(uint4*)&sBhi[r * ZST + q * 8] = *(const uint4*)(g_bwhi + go);
            *(uint4*)&sBlo[r * ZST + q * 8] = *(const uint4*)(g_bwlo + go);
        }
        __syncthreads();

#pragma unroll
        for (int ks = 0; ks < 2; ks++) {
            uint32_t ahi[2][4], alo[2][4];
#pragma unroll
            for (int mi = 0; mi < 2; mi++) {
                int rb = (wm * 32 + mi * 16 + gr) * ZST + ks * 16 + tg * 2;
                ahi[mi][0] = *(const uint32_t*)&sAhi[rb];
                ahi[mi][1] = *(const uint32_t*)&sAhi[rb + 8 * ZST];
                ahi[mi][2] = *(const uint32_t*)&sAhi[rb + 8];
                ahi[mi][3] = *(const uint32_t*)&sAhi[rb + 8 * ZST + 8];
                alo[mi][0] = *(const uint32_t*)&sAlo[rb];
                alo[mi][1] = *(const uint32_t*)&sAlo[rb + 8 * ZST];
                alo[mi][2] = *(const uint32_t*)&sAlo[rb + 8];
                alo[mi][3] = *(const uint32_t*)&sAlo[rb + 8 * ZST + 8];
            }
            uint32_t bhi[4][2], blo[4][2];
#pragma unroll
            for (int ni = 0; ni < 4; ni++) {
                int rb = (wn * 32 + ni * 8 + gr) * ZST + ks * 16 + tg * 2;
                bhi[ni][0] = *(const uint32_t*)&sBhi[rb];
                bhi[ni][1] = *(const uint32_t*)&sBhi[rb + 8];
                blo[ni][0] = *(const uint32_t*)&sBlo[rb];
                blo[ni][1] = *(const uint32_t*)&sBlo[rb + 8];
            }
#pragma unroll
            for (int mi = 0; mi < 2; mi++)
#pragma unroll
                for (int ni = 0; ni < 4; ni++) {
                    mma16816(c[mi][ni], ahi[mi], bhi[ni]);
                    mma16816(c[mi][ni], ahi[mi], blo[ni]);
                    mma16816(c[mi][ni], alo[mi], bhi[ni]);
                }
        }
    }

    const int rbase = row0 + wm * 32;
    const int cbase = n0 + wn * 32;
#pragma unroll
    for (int mi = 0; mi < 2; mi++) {
#pragma unroll
        for (int ni = 0; ni < 4; ni++) {
            int r = rbase + mi * 16 + gr;
            int col = cbase + ni * 8 + tg * 2;
            float2 b01 = *(const float2*)&g_bp[col];
            float2 v0 = make_float2(c[mi][ni][0] + b01.x, c[mi][ni][1] + b01.y);
            float2 v1 = make_float2(c[mi][ni][2] + b01.x, c[mi][ni][3] + b01.y);
            *(float2*)&g_zx[(size_t)r * NC + col] = v0;
            *(float2*)&g_zx[(size_t)(r + 8) * NC + col] = v1;
        }
    }
}

// ===========================================================================
// Persistent recurrent kernel via mma.sync (bf16x3).
// 128 CTAs x 256 threads. CTA cu owns 32 gate-cols (8 units).
// B (weights) resident in smem bf16 hi/lo [32][RPITCH]; A (h) streamed from
// global bf16 hi/lo [b][u-swizzled] ping-pong.
// 8 warps K-split x128: warp does M32 x N32 x K128 = 8 k16 x (2m x 4n) x 3.
// smem: weights 134144B + red[8][32][40] fp32 40960B = 175104B
// ===========================================================================
__global__ __launch_bounds__(256, 1) void lstm_persistent(float* __restrict__ out) {
    extern __shared__ __align__(16) char smem[];
    __nv_bfloat16* wshi = (__nv_bfloat16*)smem;          // [32][RPITCH]
    __nv_bfloat16* wslo = wshi + 32 * RPITCH;
    float* red = (float*)(smem + (size_t)32 * RPITCH * 2 * 2);  // [8][32][40]

    const int tid = threadIdx.x;
    const int cu = blockIdx.x;
    const int lane = tid & 31;
    const int wid = tid >> 5;
    const int gr = lane >> 2;
    const int tg = lane & 3;
    const int kb = wid * 128;       // warp K-slice base

    // --- load resident weights (rows c_local = 0..31 -> c = cu*32+c_local) ---
    for (int i = tid; i < 32 * 128; i += 256) {
        int lr = i >> 7, q = i & 127;
        size_t go = ((size_t)(cu * 32 + lr)) * 1024 + q * 8;
        *(uint4*)(wshi + lr * RPITCH + q * 8) = *(const uint4*)(g_rwhi + go);
        *(uint4*)(wslo + lr * RPITCH + q * 8) = *(const uint4*)(g_rwlo + go);
    }

    // --- gate-math roles ---
    const int up = tid >> 5;        // unit-in-CTA 0..7
    const int gb = tid & 31;        // batch 0..31
    const int ug = cu * 8 + up;     // global unit
    // precomputed swizzled h-store index
    const int i16 = ug & 15;
    const int hidx = (ug & ~15) + fragpos(i16);

    float c_state = 0.0f;
    __syncthreads();                // weights ready

    for (int t = 0; t < TT; t++) {
        const __nv_bfloat16* __restrict__ hhi = g_hhi[t & 1];
        const __nv_bfloat16* __restrict__ hlo = g_hlo[t & 1];
        __nv_bfloat16* __restrict__ hhio = g_hhi[(t + 1) & 1];
        __nv_bfloat16* __restrict__ hloo = g_hlo[(t + 1) & 1];

        float4 zx4 = __ldcg((const float4*)&g_zx[((size_t)t * BB + gb) * NC + ug * 4]);

        float acc[2][4][4];
#pragma unroll
        for (int mi = 0; mi < 2; mi++)
#pragma unroll
            for (int ni = 0; ni < 4; ni++)
#pragma unroll
                for (int r = 0; r < 4; r++) acc[mi][ni][r] = 0.0f;

        // A fragment loads: one LDG.64 gives (a0, a2) thanks to the u-swizzle
#define LDA(dst, u0) do { \
        (dst)[0] = __ldcg((const uint2*)(hhi + (gr)      * 1024 + (u0)) + tg); \
        (dst)[1] = __ldcg((const uint2*)(hhi + (gr + 8)  * 1024 + (u0)) + tg); \
        (dst)[2] = __ldcg((const uint2*)(hhi + (gr + 16) * 1024 + (u0)) + tg); \
        (dst)[3] = __ldcg((const uint2*)(hhi + (gr + 24) * 1024 + (u0)) + tg); \
        (dst)[4] = __ldcg((const uint2*)(hlo + (gr)      * 1024 + (u0)) + tg); \
        (dst)[5] = __ldcg((const uint2*)(hlo + (gr + 8)  * 1024 + (u0)) + tg); \
        (dst)[6] = __ldcg((const uint2*)(hlo + (gr + 16) * 1024 + (u0)) + tg); \
        (dst)[7] = __ldcg((const uint2*)(hlo + (gr + 24) * 1024 + (u0)) + tg); \
    } while (0)

#define COMPUTE(buf, k0) do { \
        uint32_t ah0[4] = {(buf)[0].x, (buf)[1].x, (buf)[0].y, (buf)[1].y}; \
        uint32_t ah1[4] = {(buf)[2].x, (buf)[3].x, (buf)[2].y, (buf)[3].y}; \
        uint32_t al0[4] = {(buf)[4].x, (buf)[5].x, (buf)[4].y, (buf)[5].y}; \
        uint32_t al1[4] = {(buf)[6].x, (buf)[7].x, (buf)[6].y, (buf)[7].y}; \
        _Pragma("unroll") \
        for (int ni = 0; ni < 4; ni++) { \
            const __nv_bfloat16* bh = wshi + (ni * 8 + gr) * RPITCH + (k0) + tg * 2; \
            const __nv_bfloat16* bl = wslo + (ni * 8 + gr) * RPITCH + (k0) + tg * 2; \
            uint32_t bhi[2] = {*(const uint32_t*)bh, *(const uint32_t*)(bh + 8)}; \
            uint32_t blo[2] = {*(const uint32_t*)bl, *(const uint32_t*)(bl + 8)}; \
            mma16816(acc[0][ni], ah0, bhi); \
            mma16816(acc[0][ni], ah0, blo); \
            mma16816(acc[0][ni], al0, bhi); \
            mma16816(acc[1][ni], ah1, bhi); \
            mma16816(acc[1][ni], ah1, blo); \
            mma16816(acc[1][ni], al1, bhi); \
        } \
    } while (0)

        uint2 cur[8], nxt[8];
        LDA(cur, kb);
#pragma unroll
        for (int i = 0; i < 8; i += 2) {
            LDA(nxt, kb + (i + 1) * 16);
            COMPUTE(cur, kb + i * 16);
            if (i + 2 < 8) LDA(cur, kb + (i + 2) * 16);
            COMPUTE(nxt, kb + (i + 1) * 16);
        }

        // ---- write partials: red[wid][b][40] ----
#pragma unroll
        for (int mi = 0; mi < 2; mi++)
#pragma unroll
            for (int ni = 0; ni < 4; ni++) {
                float* b0 = &red[((size_t)wid * 32 + mi * 16 + gr) * 40 + ni * 8 + tg * 2];
                *(float2*)b0 = make_float2(acc[mi][ni][0], acc[mi][ni][1]);
                *(float2*)(b0 + 8 * 40) = make_float2(acc[mi][ni][2], acc[mi][ni][3]);
            }
        __syncthreads();

        // ---- reduce + gate math: thread = (unit up, batch gb) ----
        float h_new;
        {
            float4 z = make_float4(0.f, 0.f, 0.f, 0.f);
#pragma unroll
            for (int s = 0; s < 8; s++) {
                float4 v = *(const float4*)&red[((size_t)s * 32 + gb) * 40 + up * 4];
                z.x += v.x; z.y += v.y; z.z += v.z; z.w += v.w;
            }
            float zf = z.x + zx4.x;
            float zi = z.y + zx4.y;
            float zg = z.z + zx4.z;
            float zo = z.w + zx4.w;

            float f = sigmoidf_(zf);
            float ii = sigmoidf_(zi);
            float g = tanhf_(zg);
            float o = sigmoidf_(zo);
            c_state = f * c_state + ii * g;
            h_new = o * tanhf_(c_state);

            __nv_bfloat16 hh = __float2bfloat16(h_new);
            __nv_bfloat16 hl = __float2bfloat16(h_new - __bfloat162float(hh));
            hhio[gb * 1024 + hidx] = hh;
            hloo[gb * 1024 + hidx] = hl;
        }

        // ---- grid barrier (release/acquire) ----
        __syncthreads();   // h stores issued, red consumed
        if (tid == 0) bar_arrive_release(&g_bar);

        out[((size_t)gb * TT + t) * UU + ug] = h_new;

        if (tid == 0) {
            unsigned target = (unsigned)NCTA * (unsigned)(t + 1);
            while (ld_acquire(&g_bar) < target) {}
        }
        __syncthreads();
    }
#undef LDA
#undef COMPUTE
}

// ===========================================================================
// Launch
// ===========================================================================
extern "C" void kernel_launch(void* const* d_in, const int* in_sizes, int n_in,
                              void* d_out, int out_size) {
    const float* data = (const float*)d_in[0];
    const float* Wf = (const float*)d_in[1];
    const float* bf = (const float*)d_in[2];
    const float* Wi = (const float*)d_in[3];
    const float* bi = (const float*)d_in[4];
    const float* Wc = (const float*)d_in[5];
    const float* bc = (const float*)d_in[6];
    const float* Wo = (const float*)d_in[7];
    const float* bo = (const float*)d_in[8];
    float* out = (float*)d_out;

    static int attr_set = 0;
    const int psmem_bytes = 32 * RPITCH * 2 * 2 + 8 * 32 * 40 * 4;  // 175104
    if (!attr_set) {
        cudaFuncSetAttribute(lstm_persistent,
                             cudaFuncAttributeMaxDynamicSharedMemorySize, psmem_bytes);
        attr_set = 1;
    }

    prep_kernel<<<512, 256>>>(Wf, Wi, Wc, Wo, bf, bi, bc, bo);
    conv_x_kernel<<<2048, 256>>>(data);

    dim3 zgrid(NC / ZNT, (TT * BB) / ZMT);  // (64, 128)
    zx_mma_kernel<<<zgrid, 256>>>();

    lstm_persistent<<<NCTA, 256, psmem_bytes>>>(out);
}